// round 2
// baseline (speedup 1.0000x reference)
#include <cuda_runtime.h>
#include <math.h>

#define BATCH 32
#define TT 4096
#define NH 100
#define NM 65
#define LAG 149               // effective delay in frames
#define H_ELEMS (BATCH*TT*NH) // 13107200
#define N_ELEMS (BATCH*TT*NM) // 8519680

// ---- scratch (static __device__, no allocation) ----
__device__ float g_turb[TT*NH];   // 1 + 0.225*sin(phase(t)+off(k))
__device__ float g_nf[TT*NM];     // 1 + 0.6*sin(ripple(m)+phase(t))
__device__ float g_cent[TT*BATCH];// per (t,b) centroid
__device__ float g_mh1[TT*NH];    // batch-mean of h1 (tension*turb)
__device__ float g_s[TT];         // 0.4*sin(clock(t))

__device__ __forceinline__ float warp_max(float v) {
    #pragma unroll
    for (int o = 16; o; o >>= 1) v = fmaxf(v, __shfl_xor_sync(0xffffffffu, v, o));
    return v;
}
__device__ __forceinline__ float warp_sum(float v) {
    #pragma unroll
    for (int o = 16; o; o >>= 1) v += __shfl_xor_sync(0xffffffffu, v, o);
    return v;
}

// ---------------- K0: factor tables (recomputed every launch; deterministic) ----------------
__global__ void k0_tables() {
    const double TWO_PI_D = 6.283185307179586;
    const double PH_INC   = TWO_PI_D * 40.0 * 64.0 / 16000.0;   // 2*pi*0.16
    const double OFF_STEP = 4.71238898038469 / 99.0;            // pi*1.5/99
    const double RIP_STEP = 7.853981633974483;                  // pi*2.5
    int total = TT*NH + TT*NM;
    for (int i = blockIdx.x*blockDim.x + threadIdx.x; i < total; i += gridDim.x*blockDim.x) {
        if (i < TT*NH) {
            int t = i / NH, k = i % NH;
            double phase = fmod((double)(t+1)*PH_INC, TWO_PI_D);
            float a = (float)fmod(phase + (double)k*OFF_STEP, TWO_PI_D);
            g_turb[i] = 1.0f + 0.225f * sinf(a);
        } else {
            int j = i - TT*NH;
            int t = j / NM, m = j % NM;
            double phase = fmod((double)(t+1)*PH_INC, TWO_PI_D);
            float a = (float)fmod((double)m*RIP_STEP + phase, TWO_PI_D);
            g_nf[j] = 1.0f + 0.6f * sinf(a);
        }
    }
}

// ---------------- K1: per-t block (32 warps = 32 batches): centroid + batch-mean of h1 ----------------
__global__ void __launch_bounds__(1024) k1_reduce(const float* __restrict__ harm) {
    int t = blockIdx.x;
    int w = threadIdx.x >> 5;      // batch index
    int lane = threadIdx.x & 31;
    const float* row = harm + ((size_t)w*TT + t)*NH;
    __shared__ float sh[32*129];   // [b][k] padded to kill bank conflicts

    float vals[4];
    float mo = 1e-6f;
    #pragma unroll
    for (int i = 0; i < 4; i++) {
        int k = lane + 32*i;
        float x = (k < NH) ? __ldg(row + k) : 0.f;
        vals[i] = x; mo = fmaxf(mo, x);
    }
    mo = warp_max(mo);
    float sharp[4]; float ms = 1e-6f;
    #pragma unroll
    for (int i = 0; i < 4; i++) {
        int k = lane + 32*i;
        float x = fmaxf(vals[i], 1e-6f);
        float sp = (k < NH) ? __expf(3.4f * __logf(x)) : 0.f;
        sharp[i] = sp; ms = fmaxf(ms, sp);
    }
    ms = warp_max(ms);
    float scale = mo / ms;

    float s0 = 0.f, s1 = 0.f;
    #pragma unroll
    for (int i = 0; i < 4; i++) {
        int k = lane + 32*i;
        float h1 = (k < NH) ? sharp[i]*scale*g_turb[t*NH + k] : 0.f;
        s0 += h1; s1 += h1 * (float)k;
        sh[w*129 + k] = h1;
    }
    s0 = warp_sum(s0); s1 = warp_sum(s1);
    if (lane == 0) g_cent[t*BATCH + w] = s1 / fmaxf(s0, 1e-6f);
    __syncthreads();
    int k = threadIdx.x;
    if (k < NH) {
        float s = 0.f;
        #pragma unroll
        for (int b = 0; b < 32; b++) s += sh[b*129 + k];   // fixed order -> deterministic
        g_mh1[t*NH + k] = s * (1.f/32.f);
    }
}

// ---------------- K2: single-block parallel scan over t (fb affine scan, clock cumsum) ----------------
__global__ void __launch_bounds__(1024) k2_scan() {
    __shared__ double shM[1024];
    __shared__ double shC[1024];
    const double TWO_PI_D = 6.283185307179586;
    const double RATE_K = 0.725 * TWO_PI_D * (64.0/16000.0);
    int tid = threadIdx.x;

    // c(t) for this thread's 4 frames
    double d[4];
    #pragma unroll
    for (int j = 0; j < 4; j++) {
        int t = tid*4 + j;
        float s = 0.f;
        #pragma unroll
        for (int b = 0; b < BATCH; b++) s += g_cent[t*BATCH + b];
        double c = (double)(s * (1.f/32.f));
        d[j] = (c - 30.0) / 400.0;   // 0.1 * ((c-30)/40)
    }
    // chunk-local affine map y -> M*y + C (4 steps of y -> 0.9y + d)
    double M = 0.9*0.9*0.9*0.9;
    double C = ((d[0]*0.9 + d[1])*0.9 + d[2])*0.9 + d[3];
    shM[tid] = M; shC[tid] = C;
    __syncthreads();
    // inclusive Hillis-Steele scan of affine maps
    for (int off = 1; off < 1024; off <<= 1) {
        double pm = 1.0, pc = 0.0; bool has = (tid >= off);
        if (has) { pm = shM[tid-off]; pc = shC[tid-off]; }
        __syncthreads();
        if (has) { double mc = shM[tid], cc = shC[tid]; shM[tid] = pm*mc; shC[tid] = pc*mc + cc; }
        __syncthreads();
    }
    double fb = (tid == 0) ? 0.0 : shC[tid-1];   // exclusive prefix applied to fb0 = 0
    __syncthreads();

    // re-walk: fb(t), rate(t), local inclusive cumsum
    double rloc[4]; double csum = 0.0;
    #pragma unroll
    for (int j = 0; j < 4; j++) {
        fb = 0.9*fb + d[j];
        double r = RATE_K * (1.0 + 0.4*fb);
        csum += r; rloc[j] = csum;
    }
    shC[tid] = csum;
    __syncthreads();
    for (int off = 1; off < 1024; off <<= 1) {
        double a = 0.0; bool has = (tid >= off);
        if (has) a = shC[tid-off];
        __syncthreads();
        if (has) shC[tid] += a;
        __syncthreads();
    }
    double base = (tid == 0) ? 0.0 : shC[tid-1];
    #pragma unroll
    for (int j = 0; j < 4; j++) {
        double clock = base + rloc[j];
        float cm = (float)fmod(clock, TWO_PI_D);
        g_s[tid*4 + j] = 0.4f * sinf(cm);
    }
}

// ---------------- K3: harmonic output (warp per (b,t) row; recompute tension) ----------------
__global__ void __launch_bounds__(256) k3_out(const float* __restrict__ harm, float* __restrict__ out) {
    int wg = (blockIdx.x * blockDim.x + threadIdx.x) >> 5;   // row = b*TT + t
    int lane = threadIdx.x & 31;
    if (wg >= BATCH*TT) return;
    int t = wg & (TT - 1);
    const float* row = harm + (size_t)wg * NH;
    float* orow = out + (size_t)wg * NH;

    float vals[4]; float mo = 1e-6f;
    #pragma unroll
    for (int i = 0; i < 4; i++) {
        int k = lane + 32*i;
        float x = (k < NH) ? __ldg(row + k) : 0.f;
        vals[i] = x; mo = fmaxf(mo, x);
    }
    mo = warp_max(mo);
    float sharp[4]; float ms = 1e-6f;
    #pragma unroll
    for (int i = 0; i < 4; i++) {
        int k = lane + 32*i;
        float x = fmaxf(vals[i], 1e-6f);
        float sp = (k < NH) ? __expf(3.4f * __logf(x)) : 0.f;
        sharp[i] = sp; ms = fmaxf(ms, sp);
    }
    ms = warp_max(ms);
    float scale = mo / ms;

    float st = g_s[t];
    bool has_mem = (t > 0);
    bool has_rd  = (t >= LAG);
    float sp_lag = has_rd ? g_s[t - LAG] : 0.f;

    #pragma unroll
    for (int i = 0; i < 4; i++) {
        int k = lane + 32*i;
        if (k < NH) {
            float h1 = sharp[i]*scale*g_turb[t*NH + k];
            float rel = (float)k * (2.f/99.f) - 1.f;
            float h2 = h1 * (1.f + st*rel);
            float o;
            if (!has_mem) {
                o = h2;
            } else {
                float m = has_rd ? (1.f + sp_lag*rel) * g_mh1[(t - LAG)*NH + k] : 0.f;
                o = 0.6f*h2 + 0.4f*m;
            }
            orow[k] = o;
        }
    }
}

// ---------------- K4: noise output (pure elementwise) ----------------
__global__ void k4_noise(const float* __restrict__ noise, float* __restrict__ out) {
    for (unsigned i = blockIdx.x*blockDim.x + threadIdx.x; i < (unsigned)N_ELEMS;
         i += gridDim.x*blockDim.x) {
        unsigned m = i % NM;
        unsigned t = (i / NM) & (TT - 1);
        out[i] = noise[i] * g_nf[t*NM + m];
    }
}

extern "C" void kernel_launch(void* const* d_in, const int* in_sizes, int n_in,
                              void* d_out, int out_size) {
    const float* harm  = (const float*)d_in[0];
    const float* noise = (const float*)d_in[1];
    float* out = (float*)d_out;

    k0_tables<<<256, 256>>>();
    k1_reduce<<<TT, 1024>>>(harm);
    k2_scan<<<1, 1024>>>();
    k3_out<<<(BATCH*TT)/8, 256>>>(harm, out);                 // 8 warps/block, warp per row
    k4_noise<<<2048, 256>>>(noise, out + H_ELEMS);
}

// round 7
// speedup vs baseline: 1.6705x; 1.6705x over previous
#include <cuda_runtime.h>
#include <math.h>

#define BATCH 32
#define TT 4096
#define NH 100
#define NH4 25
#define NM 65
#define LAG 149
#define H_ELEMS (BATCH*TT*NH)
#define N_ELEMS (BATCH*TT*NM)
#define PERIOD4 ((TT*NM)/4)    // 66560
#define K3_BLOCKS ((BATCH*TT)/8)     // 16384 (8 warps/block, warp per row)
#define K4_BLOCKS ((N_ELEMS/4)/256)  // 8320

// ---- scratch ----
__device__ float g_turb[TT*NH];    // 1 + 0.225*sin(phase(t)+off(k))
__device__ float g_nf[TT*NM];      // 1 + 0.6*sin(ripple(m)+phase(t))
__device__ float g_cmean[TT];      // batch-mean centroid per t
__device__ float g_mh1[TT*NH];     // batch-mean of h1
__device__ float g_s[TT];          // 0.4*sin(clock(t))

__device__ __forceinline__ float warp_max(float v) {
    #pragma unroll
    for (int o = 16; o; o >>= 1) v = fmaxf(v, __shfl_xor_sync(0xffffffffu, v, o));
    return v;
}
__device__ __forceinline__ float warp_sum(float v) {
    #pragma unroll
    for (int o = 16; o; o >>= 1) v += __shfl_xor_sync(0xffffffffu, v, o);
    return v;
}

// ---------------- K0: factor tables, one block per t ----------------
__global__ void __launch_bounds__(192) k0_tables() {
    const double TWO_PI_D = 6.283185307179586;
    const double PH_INC   = TWO_PI_D * 40.0 * 64.0 / 16000.0;
    int t = blockIdx.x;
    float phasef = (float)fmod((double)(t+1)*PH_INC, TWO_PI_D);
    int tid = threadIdx.x;
    if (tid < NH) {
        const float OFF_STEP = (float)(4.71238898038469 / 99.0);  // pi*1.5/99
        float a = phasef + (float)tid * OFF_STEP;
        g_turb[t*NH + tid] = 1.0f + 0.225f * sinf(a);
    } else if (tid < NH + NM) {
        int m = tid - NH;
        const float RIP_STEP = 7.853981633974483f;                // pi*2.5
        float a = (float)m * RIP_STEP + phasef;
        g_nf[t*NM + m] = 1.0f + 0.6f * sinf(a);
    }
}

// ---------------- K1: one t per block (32 warps = 32 batches) ----------------
// Produces: g_cmean[t] (batch-mean centroid), g_mh1[t*NH+k] (batch-mean h1)
__global__ void __launch_bounds__(1024) k1_reduce(const float* __restrict__ harm) {
    int t = blockIdx.x;
    int w = threadIdx.x >> 5;          // batch index
    int lane = threadIdx.x & 31;
    const float4* row4 = (const float4*)(harm + ((size_t)w*TT + t)*NH);
    const float4* turb4 = (const float4*)(g_turb + (size_t)t*NH);

    __shared__ float sh[32*104];       // [b][k] h1 values, stride 104 (16B-aligned rows)
    __shared__ float scent[32];

    float4 v = make_float4(0.f,0.f,0.f,0.f);
    bool act = (lane < NH4);
    if (act) v = __ldg(row4 + lane);
    float mo = 1e-6f;
    mo = fmaxf(fmaxf(fmaxf(mo, v.x), fmaxf(v.y, v.z)), v.w);
    if (!act) mo = 1e-6f;
    mo = warp_max(mo);

    float4 sp;
    sp.x = exp2f(3.4f * __log2f(fmaxf(v.x, 1e-6f)));
    sp.y = exp2f(3.4f * __log2f(fmaxf(v.y, 1e-6f)));
    sp.z = exp2f(3.4f * __log2f(fmaxf(v.z, 1e-6f)));
    sp.w = exp2f(3.4f * __log2f(fmaxf(v.w, 1e-6f)));
    float ms = act ? fmaxf(fmaxf(sp.x, sp.y), fmaxf(sp.z, sp.w)) : 1e-6f;
    ms = fmaxf(ms, 1e-6f);
    ms = warp_max(ms);
    float scale = mo / ms;

    float4 h1 = make_float4(0.f,0.f,0.f,0.f);
    float s0 = 0.f, s1 = 0.f;
    if (act) {
        float4 tb = turb4[lane];
        h1.x = sp.x * scale * tb.x;
        h1.y = sp.y * scale * tb.y;
        h1.z = sp.z * scale * tb.z;
        h1.w = sp.w * scale * tb.w;
        float k0 = (float)(lane*4);
        s0 = h1.x + h1.y + h1.z + h1.w;
        s1 = h1.x*k0 + h1.y*(k0+1.f) + h1.z*(k0+2.f) + h1.w*(k0+3.f);
    }
    s0 = warp_sum(s0); s1 = warp_sum(s1);
    if (lane == 0) scent[w] = s1 / fmaxf(s0, 1e-6f);
    if (act) ((float4*)&sh[w*104])[lane] = h1;
    __syncthreads();

    if (w == 0) {                      // batch-mean centroid
        float c = scent[lane];
        c = warp_sum(c);
        if (lane == 0) g_cmean[t] = c * (1.f/32.f);
    }
    int k = threadIdx.x;
    if (k < NH) {                      // batch-mean h1, fixed order -> deterministic
        float s = 0.f;
        #pragma unroll
        for (int b = 0; b < 32; b++) s += sh[b*104 + k];
        g_mh1[t*NH + k] = s * (1.f/32.f);
    }
}

// ---------------- K2: single-block scan over t ----------------
__global__ void __launch_bounds__(1024) k2_scan() {
    __shared__ double shM[1024];
    __shared__ double shC[1024];
    const double TWO_PI_D = 6.283185307179586;
    const double RATE_K = 0.725 * TWO_PI_D * (64.0/16000.0);
    int tid = threadIdx.x;

    double d[4];
    #pragma unroll
    for (int j = 0; j < 4; j++) {
        double c = (double)g_cmean[tid*4 + j];
        d[j] = (c - 30.0) / 400.0;
    }
    double M = 0.9*0.9*0.9*0.9;
    double C = ((d[0]*0.9 + d[1])*0.9 + d[2])*0.9 + d[3];
    shM[tid] = M; shC[tid] = C;
    __syncthreads();
    for (int off = 1; off < 1024; off <<= 1) {
        double pm = 1.0, pc = 0.0; bool has = (tid >= off);
        if (has) { pm = shM[tid-off]; pc = shC[tid-off]; }
        __syncthreads();
        if (has) { double mc = shM[tid], cc = shC[tid]; shM[tid] = pm*mc; shC[tid] = pc*mc + cc; }
        __syncthreads();
    }
    double fb = (tid == 0) ? 0.0 : shC[tid-1];
    __syncthreads();

    double rloc[4]; double csum = 0.0;
    #pragma unroll
    for (int j = 0; j < 4; j++) {
        fb = 0.9*fb + d[j];
        double r = RATE_K * (1.0 + 0.4*fb);
        csum += r; rloc[j] = csum;
    }
    shC[tid] = csum;
    __syncthreads();
    for (int off = 1; off < 1024; off <<= 1) {
        double a = 0.0; bool has = (tid >= off);
        if (has) a = shC[tid-off];
        __syncthreads();
        if (has) shC[tid] += a;
        __syncthreads();
    }
    double base = (tid == 0) ? 0.0 : shC[tid-1];
    #pragma unroll
    for (int j = 0; j < 4; j++) {
        double clock = base + rloc[j];
        float cm = (float)fmod(clock, TWO_PI_D);
        g_s[tid*4 + j] = 0.4f * sinf(cm);
    }
}

// ---------------- K34: fused output kernel ----------------
// blocks [0, K3_BLOCKS): harmonic path (warp per (b,t) row, float4)
// blocks [K3_BLOCKS, K3_BLOCKS+K4_BLOCKS): noise path (float4 elementwise)
__global__ void __launch_bounds__(256) k34_out(const float* __restrict__ harm,
                                               const float4* __restrict__ noise,
                                               float* __restrict__ out) {
    if (blockIdx.x < K3_BLOCKS) {
        // ---- harmonic path ----
        int wg = (blockIdx.x * 256 + threadIdx.x) >> 5;   // row = b*TT + t
        int lane = threadIdx.x & 31;
        int t = wg & (TT - 1);
        const float4* row4  = (const float4*)(harm + (size_t)wg * NH);
        float4*       orow4 = (float4*)(out + (size_t)wg * NH);
        const float4* turb4 = (const float4*)(g_turb + (size_t)t*NH);

        bool act = (lane < NH4);
        float4 v = make_float4(0.f,0.f,0.f,0.f);
        if (act) v = __ldg(row4 + lane);
        float mo = fmaxf(fmaxf(fmaxf(1e-6f, v.x), fmaxf(v.y, v.z)), v.w);
        if (!act) mo = 1e-6f;
        mo = warp_max(mo);

        float4 sp;
        sp.x = exp2f(3.4f * __log2f(fmaxf(v.x, 1e-6f)));
        sp.y = exp2f(3.4f * __log2f(fmaxf(v.y, 1e-6f)));
        sp.z = exp2f(3.4f * __log2f(fmaxf(v.z, 1e-6f)));
        sp.w = exp2f(3.4f * __log2f(fmaxf(v.w, 1e-6f)));
        float ms = act ? fmaxf(fmaxf(sp.x, sp.y), fmaxf(sp.z, sp.w)) : 1e-6f;
        ms = fmaxf(ms, 1e-6f);
        ms = warp_max(ms);
        float scale = mo / ms;

        float st = g_s[t];
        bool has_mem = (t > 0);
        bool has_rd  = (t >= LAG);
        float sp_lag = has_rd ? g_s[t - LAG] : 0.f;

        if (act) {
            float4 tb = turb4[lane];
            float k0 = (float)(lane*4);
            float relx = k0*(2.f/99.f) - 1.f;
            float rely = (k0+1.f)*(2.f/99.f) - 1.f;
            float relz = (k0+2.f)*(2.f/99.f) - 1.f;
            float relw = (k0+3.f)*(2.f/99.f) - 1.f;

            float4 h2;
            h2.x = sp.x*scale*tb.x * (1.f + st*relx);
            h2.y = sp.y*scale*tb.y * (1.f + st*rely);
            h2.z = sp.z*scale*tb.z * (1.f + st*relz);
            h2.w = sp.w*scale*tb.w * (1.f + st*relw);

            float4 o;
            if (!has_mem) {
                o = h2;
            } else if (has_rd) {
                const float4* mh4 = (const float4*)(g_mh1 + (size_t)(t - LAG)*NH);
                float4 m = mh4[lane];
                o.x = 0.6f*h2.x + 0.4f*(1.f + sp_lag*relx)*m.x;
                o.y = 0.6f*h2.y + 0.4f*(1.f + sp_lag*rely)*m.y;
                o.z = 0.6f*h2.z + 0.4f*(1.f + sp_lag*relz)*m.z;
                o.w = 0.6f*h2.w + 0.4f*(1.f + sp_lag*relw)*m.w;
            } else {
                o.x = 0.6f*h2.x; o.y = 0.6f*h2.y; o.z = 0.6f*h2.z; o.w = 0.6f*h2.w;
            }
            orow4[lane] = o;
        }
    } else {
        // ---- noise path ----
        unsigned i4 = (blockIdx.x - K3_BLOCKS) * 256 + threadIdx.x;  // < N_ELEMS/4
        unsigned p = i4 % PERIOD4;
        float4* nout4 = (float4*)(out + H_ELEMS);
        float4 n = __ldg(noise + i4);
        float4 f = ((const float4*)g_nf)[p];
        float4 o;
        o.x = n.x*f.x; o.y = n.y*f.y; o.z = n.z*f.z; o.w = n.w*f.w;
        nout4[i4] = o;
    }
}

extern "C" void kernel_launch(void* const* d_in, const int* in_sizes, int n_in,
                              void* d_out, int out_size) {
    const float* harm  = (const float*)d_in[0];
    const float* noise = (const float*)d_in[1];
    float* out = (float*)d_out;

    k0_tables<<<TT, 192>>>();
    k1_reduce<<<TT, 1024>>>(harm);
    k2_scan<<<1, 1024>>>();
    k34_out<<<K3_BLOCKS + K4_BLOCKS, 256>>>(harm, (const float4*)noise, out);
}

// round 11
// speedup vs baseline: 1.8741x; 1.1219x over previous
#include <cuda_runtime.h>
#include <math.h>

#define BATCH 32
#define TT 4096
#define NH 100
#define NH4 25
#define NM 65
#define LAG 149
#define H_ELEMS (BATCH*TT*NH)
#define N_ELEMS (BATCH*TT*NM)
#define PERIOD4 ((TT*NM)/4)          // 66560
#define K3_BLOCKS ((BATCH*TT)/8)     // 16384 (8 warps/block, warp per row)
#define K4_BLOCKS ((N_ELEMS/4)/256)  // 8320

// ---- scratch ----
__device__ float g_turb[TT*NH];    // 1 + 0.225*sin(phase(t)+off(k))
__device__ float g_nf[TT*NM];      // 1 + 0.6*sin(ripple(m)+phase(t))
__device__ float g_cmean[TT];      // batch-mean centroid per t
__device__ float g_mh1[TT*NH];     // batch-mean of h1
__device__ float g_s[TT];          // 0.4*sin(clock(t))

__device__ __forceinline__ float warp_max(float v) {
    #pragma unroll
    for (int o = 16; o; o >>= 1) v = fmaxf(v, __shfl_xor_sync(0xffffffffu, v, o));
    return v;
}
__device__ __forceinline__ float warp_sum(float v) {
    #pragma unroll
    for (int o = 16; o; o >>= 1) v += __shfl_xor_sync(0xffffffffu, v, o);
    return v;
}

// ---------------- K1: one t per block (256 thr, 8 warps x 4 batches) ----------------
// Also builds the turb/nf factor tables for this t (K0 fused in).
// Produces: g_turb[t], g_nf[t], g_cmean[t], g_mh1[t*NH+k]
__global__ void __launch_bounds__(256) k1_reduce(const float* __restrict__ harm) {
    int t = blockIdx.x;
    int w = threadIdx.x >> 5;
    int lane = threadIdx.x & 31;
    int tid = threadIdx.x;

    __shared__ float sturb[104];     // turb row for this t (16B-aligned rows)
    __shared__ float part[8*104];    // per-warp partial sums of h1
    __shared__ float cent[32];       // per-batch centroid

    const double TWO_PI_D = 6.283185307179586;
    const double PH_INC   = TWO_PI_D * 40.0 * 64.0 / 16000.0;
    float phasef = (float)fmod((double)(t+1)*PH_INC, TWO_PI_D);

    if (tid < NH) {
        const float OFF_STEP = (float)(4.71238898038469 / 99.0);  // pi*1.5/99
        float v = 1.0f + 0.225f * sinf(phasef + (float)tid * OFF_STEP);
        sturb[tid] = v;
        g_turb[t*NH + tid] = v;
    } else if (tid < NH + NM) {
        int m = tid - NH;
        const float RIP_STEP = 7.853981633974483f;                // pi*2.5
        g_nf[t*NM + m] = 1.0f + 0.6f * sinf((float)m * RIP_STEP + phasef);
    }
    __syncthreads();

    bool act = (lane < NH4);
    float4 tb = make_float4(0.f,0.f,0.f,0.f);
    if (act) tb = ((const float4*)sturb)[lane];

    float4 acc = make_float4(0.f,0.f,0.f,0.f);
    #pragma unroll
    for (int j = 0; j < 4; j++) {
        int b = w*4 + j;
        const float4* row4 = (const float4*)(harm + ((size_t)b*TT + t)*NH);
        float4 v = make_float4(0.f,0.f,0.f,0.f);
        if (act) v = __ldg(row4 + lane);
        float mo = act ? fmaxf(fmaxf(fmaxf(1e-6f, v.x), fmaxf(v.y, v.z)), v.w) : 1e-6f;
        mo = warp_max(mo);
        // max(sharp) = mo^3.4 (monotone power), clamped like the reference
        float ms = fmaxf(exp2f(3.4f * __log2f(mo)), 1e-6f);
        float scale = mo / ms;

        float4 h1 = make_float4(0.f,0.f,0.f,0.f);
        float s0 = 0.f, s1 = 0.f;
        if (act) {
            h1.x = exp2f(3.4f * __log2f(fmaxf(v.x, 1e-6f))) * scale * tb.x;
            h1.y = exp2f(3.4f * __log2f(fmaxf(v.y, 1e-6f))) * scale * tb.y;
            h1.z = exp2f(3.4f * __log2f(fmaxf(v.z, 1e-6f))) * scale * tb.z;
            h1.w = exp2f(3.4f * __log2f(fmaxf(v.w, 1e-6f))) * scale * tb.w;
            float k0 = (float)(lane*4);
            s0 = h1.x + h1.y + h1.z + h1.w;
            s1 = h1.x*k0 + h1.y*(k0+1.f) + h1.z*(k0+2.f) + h1.w*(k0+3.f);
        }
        s0 = warp_sum(s0); s1 = warp_sum(s1);
        if (lane == 0) cent[b] = s1 / fmaxf(s0, 1e-6f);
        acc.x += h1.x; acc.y += h1.y; acc.z += h1.z; acc.w += h1.w;
    }
    if (act) ((float4*)&part[w*104])[lane] = acc;
    __syncthreads();

    if (tid < NH) {                  // 8-way partial reduce, fixed order
        float s = 0.f;
        #pragma unroll
        for (int p = 0; p < 8; p++) s += part[p*104 + tid];
        g_mh1[t*NH + tid] = s * (1.f/32.f);
    }
    if (w == 0) {                    // batch-mean centroid
        float c = cent[lane];
        c = warp_sum(c);
        if (lane == 0) g_cmean[t] = c * (1.f/32.f);
    }
}

// ---------------- K2: single-block scan over t ----------------
__global__ void __launch_bounds__(1024) k2_scan() {
    __shared__ double shM[1024];
    __shared__ double shC[1024];
    const double TWO_PI_D = 6.283185307179586;
    const double RATE_K = 0.725 * TWO_PI_D * (64.0/16000.0);
    int tid = threadIdx.x;

    double d[4];
    #pragma unroll
    for (int j = 0; j < 4; j++) {
        double c = (double)g_cmean[tid*4 + j];
        d[j] = (c - 30.0) / 400.0;
    }
    double M = 0.9*0.9*0.9*0.9;
    double C = ((d[0]*0.9 + d[1])*0.9 + d[2])*0.9 + d[3];
    shM[tid] = M; shC[tid] = C;
    __syncthreads();
    for (int off = 1; off < 1024; off <<= 1) {
        double pm = 1.0, pc = 0.0; bool has = (tid >= off);
        if (has) { pm = shM[tid-off]; pc = shC[tid-off]; }
        __syncthreads();
        if (has) { double mc = shM[tid], cc = shC[tid]; shM[tid] = pm*mc; shC[tid] = pc*mc + cc; }
        __syncthreads();
    }
    double fb = (tid == 0) ? 0.0 : shC[tid-1];
    __syncthreads();

    double rloc[4]; double csum = 0.0;
    #pragma unroll
    for (int j = 0; j < 4; j++) {
        fb = 0.9*fb + d[j];
        double r = RATE_K * (1.0 + 0.4*fb);
        csum += r; rloc[j] = csum;
    }
    shC[tid] = csum;
    __syncthreads();
    for (int off = 1; off < 1024; off <<= 1) {
        double a = 0.0; bool has = (tid >= off);
        if (has) a = shC[tid-off];
        __syncthreads();
        if (has) shC[tid] += a;
        __syncthreads();
    }
    double base = (tid == 0) ? 0.0 : shC[tid-1];
    #pragma unroll
    for (int j = 0; j < 4; j++) {
        double clock = base + rloc[j];
        float cm = (float)fmod(clock, TWO_PI_D);
        g_s[tid*4 + j] = 0.4f * sinf(cm);
    }
}

// ---------------- K34: fused output kernel ----------------
__global__ void __launch_bounds__(256) k34_out(const float* __restrict__ harm,
                                               const float4* __restrict__ noise,
                                               float* __restrict__ out) {
    if (blockIdx.x < K3_BLOCKS) {
        // ---- harmonic path: warp per (b,t) row ----
        int wg = (blockIdx.x * 256 + threadIdx.x) >> 5;   // row = b*TT + t
        int lane = threadIdx.x & 31;
        int t = wg & (TT - 1);
        const float4* row4  = (const float4*)(harm + (size_t)wg * NH);
        float4*       orow4 = (float4*)(out + (size_t)wg * NH);
        const float4* turb4 = (const float4*)(g_turb + (size_t)t*NH);

        bool act = (lane < NH4);
        float4 v = make_float4(0.f,0.f,0.f,0.f);
        if (act) v = __ldg(row4 + lane);
        float mo = act ? fmaxf(fmaxf(fmaxf(1e-6f, v.x), fmaxf(v.y, v.z)), v.w) : 1e-6f;
        mo = warp_max(mo);
        float ms = fmaxf(exp2f(3.4f * __log2f(mo)), 1e-6f);
        float scale = mo / ms;

        float st = g_s[t];
        bool has_mem = (t > 0);
        bool has_rd  = (t >= LAG);
        float sp_lag = has_rd ? g_s[t - LAG] : 0.f;

        if (act) {
            float4 tb = turb4[lane];
            float4 sp;
            sp.x = exp2f(3.4f * __log2f(fmaxf(v.x, 1e-6f)));
            sp.y = exp2f(3.4f * __log2f(fmaxf(v.y, 1e-6f)));
            sp.z = exp2f(3.4f * __log2f(fmaxf(v.z, 1e-6f)));
            sp.w = exp2f(3.4f * __log2f(fmaxf(v.w, 1e-6f)));

            float k0 = (float)(lane*4);
            float relx = k0*(2.f/99.f) - 1.f;
            float rely = (k0+1.f)*(2.f/99.f) - 1.f;
            float relz = (k0+2.f)*(2.f/99.f) - 1.f;
            float relw = (k0+3.f)*(2.f/99.f) - 1.f;

            float4 h2;
            h2.x = sp.x*scale*tb.x * (1.f + st*relx);
            h2.y = sp.y*scale*tb.y * (1.f + st*rely);
            h2.z = sp.z*scale*tb.z * (1.f + st*relz);
            h2.w = sp.w*scale*tb.w * (1.f + st*relw);

            float4 o;
            if (!has_mem) {
                o = h2;
            } else if (has_rd) {
                const float4* mh4 = (const float4*)(g_mh1 + (size_t)(t - LAG)*NH);
                float4 m = mh4[lane];
                o.x = 0.6f*h2.x + 0.4f*(1.f + sp_lag*relx)*m.x;
                o.y = 0.6f*h2.y + 0.4f*(1.f + sp_lag*rely)*m.y;
                o.z = 0.6f*h2.z + 0.4f*(1.f + sp_lag*relz)*m.z;
                o.w = 0.6f*h2.w + 0.4f*(1.f + sp_lag*relw)*m.w;
            } else {
                o.x = 0.6f*h2.x; o.y = 0.6f*h2.y; o.z = 0.6f*h2.z; o.w = 0.6f*h2.w;
            }
            orow4[lane] = o;
        }
    } else {
        // ---- noise path: float4 elementwise ----
        unsigned i4 = (blockIdx.x - K3_BLOCKS) * 256 + threadIdx.x;  // < N_ELEMS/4
        unsigned p = i4 % PERIOD4;
        float4* nout4 = (float4*)(out + H_ELEMS);
        float4 n = __ldg(noise + i4);
        float4 f = ((const float4*)g_nf)[p];
        float4 o;
        o.x = n.x*f.x; o.y = n.y*f.y; o.z = n.z*f.z; o.w = n.w*f.w;
        nout4[i4] = o;
    }
}

extern "C" void kernel_launch(void* const* d_in, const int* in_sizes, int n_in,
                              void* d_out, int out_size) {
    const float* harm  = (const float*)d_in[0];
    const float* noise = (const float*)d_in[1];
    float* out = (float*)d_out;

    k1_reduce<<<TT, 256>>>(harm);
    k2_scan<<<1, 1024>>>();
    k34_out<<<K3_BLOCKS + K4_BLOCKS, 256>>>(harm, (const float4*)noise, out);
}